// round 13
// baseline (speedup 1.0000x reference)
#include <cuda_runtime.h>
#include <cuda_fp16.h>
#include <cstddef>

#define NMAX 100000
#define EMAX 1600000
#define FDIM 128

// ---------------- static scratch (no allocs allowed) ----------------
__device__ float    g_s[NMAX];            // row exp-sum (unnormalized)
__device__ float    g_rowsum[NMAX];       // rowsum of adj .* P (UNnormalized)
__device__ int      g_count[NMAX];        // row degree
__device__ int      g_off[NMAX + 1];      // CSR offsets
__device__ int      g_bsum[1024];         // scan block sums
__device__ float    g_feat1[NMAX];
__device__ float    g_feat2[NMAX];
__device__ float    g_ev[EMAX];           // exp(leaky(e)) per edge (COO order)
__device__ unsigned short g_rank[EMAX];   // within-row rank of each edge
__device__ int2     g_cu[EMAX];           // CSR interleaved (col, normalized u-bits)
__device__ __align__(256) __half g_xh[(size_t)NMAX * FDIM];  // fp16 copy of x
__device__ __align__(256) __half g_hA[(size_t)NMAX * FDIM];  // fp16 update hop1
__device__ __align__(256) __half g_hB[(size_t)NMAX * FDIM];  // fp16 update hop2

// ---------------- kernels ----------------

// feat1/feat2 dot products + fused x->fp16 conversion + per-row state init.
__global__ void k_feats(const float* __restrict__ x, const float* __restrict__ a, int n) {
    int gw = (blockIdx.x * blockDim.x + threadIdx.x) >> 5;
    int lane = threadIdx.x & 31;
    if (gw >= n) return;
    float4 v  = __ldg((const float4*)(x + (size_t)gw * FDIM) + lane);
    float4 a1 = __ldg((const float4*)a + lane);
    float4 a2 = __ldg((const float4*)(a + FDIM) + lane);

    __half2 h0 = __floats2half2_rn(v.x, v.y);
    __half2 h1 = __floats2half2_rn(v.z, v.w);
    uint2 packed;
    packed.x = *(unsigned*)&h0;
    packed.y = *(unsigned*)&h1;
    ((uint2*)g_xh)[(size_t)gw * 32 + lane] = packed;

    float d1 = v.x * a1.x + v.y * a1.y + v.z * a1.z + v.w * a1.w;
    float d2 = v.x * a2.x + v.y * a2.y + v.z * a2.z + v.w * a2.w;
    #pragma unroll
    for (int o = 16; o; o >>= 1) {
        d1 += __shfl_down_sync(0xffffffffu, d1, o);
        d2 += __shfl_down_sync(0xffffffffu, d2, o);
    }
    if (lane == 0) {
        g_feat1[gw] = d1; g_feat2[gw] = d2;
        g_s[gw] = 0.f; g_rowsum[gw] = 0.f; g_count[gw] = 0;
    }
}

// edge pass: exp(leaky(e)), row sum, degree+rank, unnormalized rowsum
__global__ void k_edge1(const int* __restrict__ row, const int* __restrict__ col,
                        const float* __restrict__ adj, int e) {
    int j = blockIdx.x * blockDim.x + threadIdx.x;
    if (j >= e) return;
    int r = row[j];
    float ev = __ldg(&g_feat1[r]) + __ldg(&g_feat2[col[j]]);
    ev = (ev >= 0.f) ? ev : 0.2f * ev;
    float ex = __expf(ev);
    g_ev[j] = ex;
    atomicAdd(&g_s[r], ex);
    atomicAdd(&g_rowsum[r], 0.5f * adj[j] * ex);
    int rank = atomicAdd(&g_count[r], 1);
    g_rank[j] = (unsigned short)rank;
}

// scan 1: warp-shuffle per-1024-block exclusive scan of degrees
__global__ void k_scan1(int n) {
    __shared__ int warp_tot[32];
    int i = blockIdx.x * 1024 + threadIdx.x;
    int lane = threadIdx.x & 31, wid = threadIdx.x >> 5;
    int v = (i < n) ? g_count[i] : 0;
    int s = v;
    #pragma unroll
    for (int o = 1; o < 32; o <<= 1) {
        int t = __shfl_up_sync(0xffffffffu, s, o);
        if (lane >= o) s += t;
    }
    if (lane == 31) warp_tot[wid] = s;
    __syncthreads();
    if (wid == 0) {
        int w = warp_tot[lane];
        #pragma unroll
        for (int o = 1; o < 32; o <<= 1) {
            int t = __shfl_up_sync(0xffffffffu, w, o);
            if (lane >= o) w += t;
        }
        warp_tot[lane] = w;
    }
    __syncthreads();
    int base = wid ? warp_tot[wid - 1] : 0;
    if (i < n) g_off[i] = base + s - v;            // exclusive
    if (threadIdx.x == 1023) g_bsum[blockIdx.x] = base + s;
}

// scan 2+3 fused; 256 threads/block, 4 offsets per thread (smaller wave)
__global__ void k_scan23(int nb, int n) {
    __shared__ int s_prefix;
    int b = blockIdx.x;
    if (threadIdx.x < 32) {
        int acc = 0;
        for (int i = threadIdx.x; i < b; i += 32) acc += g_bsum[i];
        #pragma unroll
        for (int o = 16; o; o >>= 1) acc += __shfl_down_sync(0xffffffffu, acc, o);
        if (threadIdx.x == 0) s_prefix = acc;
    }
    __syncthreads();
    int prefix = s_prefix;
    #pragma unroll
    for (int k = 0; k < 4; k++) {
        int i = b * 1024 + k * 256 + threadIdx.x;
        if (i < n) g_off[i] += prefix;
    }
    if (b == nb - 1 && threadIdx.x == 0) g_off[n] = prefix + g_bsum[nb - 1];
}

// scatter: normalized u into interleaved CSR. No atomics.
__global__ void k_scatter(const int* __restrict__ row, const int* __restrict__ col, int e) {
    int j = blockIdx.x * blockDim.x + threadIdx.x;
    if (j >= e) return;
    int r = row[j];
    float u = g_ev[j] / __ldg(&g_s[r]);
    int pos = __ldg(&g_off[r]) + (int)g_rank[j];
    int2 cu;
    cu.x = col[j];
    cu.y = __float_as_int(u);
    g_cu[pos] = cu;
}

// ---- SpMM helpers ----

// Gather one row's edges: first tile preloaded in cu0; remainder (rare) loops.
__device__ __forceinline__ float4 row_gather(const uint2* __restrict__ in_upd, int lane,
                                             int beg, int deg, int2 cu0) {
    float4 acc = make_float4(0.f, 0.f, 0.f, 0.f);
    int m = min(32, deg);
    #pragma unroll 8
    for (int t = 0; t < m; t++) {
        int   cc = __shfl_sync(0xffffffffu, cu0.x, t);
        float uu = __int_as_float(__shfl_sync(0xffffffffu, cu0.y, t));
        uint2 raw = __ldg(in_upd + (size_t)cc * 32 + lane);
        float2 f0 = __half22float2(*(__half2*)&raw.x);
        float2 f1 = __half22float2(*(__half2*)&raw.y);
        acc.x += uu * f0.x;
        acc.y += uu * f0.y;
        acc.z += uu * f1.x;
        acc.w += uu * f1.y;
    }
    for (int j0 = 32; j0 < deg; j0 += 32) {       // rare: degree > 32
        int2 cu = make_int2(0, 0);
        if (j0 + lane < deg) cu = __ldg(&g_cu[beg + j0 + lane]);
        int mm = min(32, deg - j0);
        #pragma unroll 8
        for (int t = 0; t < mm; t++) {
            int   cc = __shfl_sync(0xffffffffu, cu.x, t);
            float uu = __int_as_float(__shfl_sync(0xffffffffu, cu.y, t));
            uint2 raw = __ldg(in_upd + (size_t)cc * 32 + lane);
            float2 f0 = __half22float2(*(__half2*)&raw.x);
            float2 f1 = __half22float2(*(__half2*)&raw.y);
            acc.x += uu * f0.x;
            acc.y += uu * f0.y;
            acc.z += uu * f1.x;
            acc.w += uu * f1.y;
        }
    }
    return acc;
}

__device__ __forceinline__ void row_epilogue(int r, int lane, int step, float4 acc,
                                             float* __restrict__ out, float c0, float c1) {
    size_t v2idx = (size_t)r * 32 + lane;
    if (step < 2) {
        __half2 h0 = __floats2half2_rn(acc.x, acc.y);
        __half2 h1 = __floats2half2_rn(acc.z, acc.w);
        uint2 packed;
        packed.x = *(unsigned*)&h0;
        packed.y = *(unsigned*)&h1;
        ((uint2*)(step == 0 ? g_hA : g_hB))[v2idx] = packed;
    } else {
        float s = __ldg(&g_s[r]);
        float inv_s = (s > 0.f) ? 1.f / s : 0.f;
        float rs0 = __ldg(&g_rowsum[r]) * inv_s;
        float rs1 = rs0 * c0;
        float rs2 = rs1 * c1;
        float w0 = 0.009f * (1.f - 0.9f * rs0);
        float w1 = 0.09f  * (1.f - 0.9f * rs1);
        float w2 = 0.9f   * (1.f - 0.9f * rs2);

        uint2 rawx = ((const uint2*)g_xh)[v2idx];
        uint2 rawa = ((const uint2*)g_hA)[v2idx];
        uint2 rawb = ((const uint2*)g_hB)[v2idx];
        float2 x0 = __half22float2(*(__half2*)&rawx.x);
        float2 x1 = __half22float2(*(__half2*)&rawx.y);
        float2 a0 = __half22float2(*(__half2*)&rawa.x);
        float2 a1 = __half22float2(*(__half2*)&rawa.y);
        float2 b0 = __half22float2(*(__half2*)&rawb.x);
        float2 b1 = __half22float2(*(__half2*)&rawb.y);
        float4 o;
        o.x = 0.001f * x0.x + w0 * a0.x + w1 * b0.x + w2 * acc.x;
        o.y = 0.001f * x0.y + w0 * a0.y + w1 * b0.y + w2 * acc.y;
        o.z = 0.001f * x1.x + w0 * a1.x + w1 * b1.x + w2 * acc.z;
        o.w = 0.001f * x1.y + w0 * a1.y + w1 * b1.y + w2 * acc.w;
        ((float4*)out)[(size_t)r * (FDIM / 4) + lane] = o;
    }
}

// fused SpMM: FOUR rows per warp, processed sequentially; all four rows'
// metadata (consecutive off values + first cu tiles) prefetched up front.
__global__ void __launch_bounds__(256) k_spmm(float* __restrict__ out,
                                              const float* __restrict__ cheb,
                                              int step, int n) {
    int warp = (blockIdx.x * blockDim.x + threadIdx.x) >> 5;
    int lane = threadIdx.x & 31;
    int r0 = warp * 4;
    if (r0 >= n) return;

    const uint2* in_upd = (const uint2*)((step == 0) ? g_xh : ((step == 1) ? g_hA : g_hB));

    // prefetch offsets for 4 consecutive rows (5 consecutive ints)
    int o0 = __ldg(&g_off[r0]);
    int o1 = __ldg(&g_off[r0 + 1]);
    int o2 = (r0 + 1 < n) ? __ldg(&g_off[r0 + 2]) : o1;
    int o3 = (r0 + 2 < n) ? __ldg(&g_off[r0 + 3]) : o2;
    int o4 = (r0 + 3 < n) ? __ldg(&g_off[r0 + 4]) : o3;
    int d0 = o1 - o0, d1 = o2 - o1, d2 = o3 - o2, d3 = o4 - o3;

    // prefetch first cu tile of each row, back-to-back
    int2 cu0 = make_int2(0, 0), cu1 = make_int2(0, 0);
    int2 cu2 = make_int2(0, 0), cu3 = make_int2(0, 0);
    if (lane < d0) cu0 = __ldg(&g_cu[o0 + lane]);
    if (lane < d1) cu1 = __ldg(&g_cu[o1 + lane]);
    if (lane < d2) cu2 = __ldg(&g_cu[o2 + lane]);
    if (lane < d3) cu3 = __ldg(&g_cu[o3 + lane]);

    float c0 = 0.f, c1 = 0.f;
    if (step == 2) {
        c0 = 1.f / (1.f + __expf(-__ldg(&cheb[0])));
        c1 = 1.f / (1.f + __expf(-__ldg(&cheb[1])));
    }

    float4 acc = row_gather(in_upd, lane, o0, d0, cu0);
    row_epilogue(r0, lane, step, acc, out, c0, c1);
    if (r0 + 1 < n) {
        acc = row_gather(in_upd, lane, o1, d1, cu1);
        row_epilogue(r0 + 1, lane, step, acc, out, c0, c1);
    }
    if (r0 + 2 < n) {
        acc = row_gather(in_upd, lane, o2, d2, cu2);
        row_epilogue(r0 + 2, lane, step, acc, out, c0, c1);
    }
    if (r0 + 3 < n) {
        acc = row_gather(in_upd, lane, o3, d3, cu3);
        row_epilogue(r0 + 3, lane, step, acc, out, c0, c1);
    }
}

// ---------------- launch ----------------
extern "C" void kernel_launch(void* const* d_in, const int* in_sizes, int n_in,
                              void* d_out, int out_size) {
    const float* x    = (const float*)d_in[0];
    const float* a    = (const float*)d_in[2];
    const float* cheb = (const float*)d_in[4];
    const float* adj  = (const float*)d_in[5];
    const int*   row  = (const int*)d_in[6];
    const int*   col  = (const int*)d_in[7];
    float* out = (float*)d_out;

    int n = in_sizes[0] / FDIM;
    int e = in_sizes[5];

    k_feats<<<((size_t)n * 32 + 255) / 256, 256>>>(x, a, n);
    k_edge1<<<(e + 255) / 256, 256>>>(row, col, adj, e);

    int nb = (n + 1023) / 1024;
    k_scan1<<<nb, 1024>>>(n);
    k_scan23<<<nb, 256>>>(nb, n);

    k_scatter<<<(e + 255) / 256, 256>>>(row, col, e);

    // 8 warps/block, 4 rows per warp -> 32 rows per block
    int spmm_blocks = (n + 31) / 32;
    for (int step = 0; step < 3; step++)
        k_spmm<<<spmm_blocks, 256>>>(out, cheb, step, n);
}

// round 14
// speedup vs baseline: 1.1616x; 1.1616x over previous
#include <cuda_runtime.h>
#include <cuda_fp16.h>
#include <cstddef>

#define NMAX 100000
#define EMAX 1600000
#define FDIM 128

// ---------------- static scratch (no allocs allowed) ----------------
__device__ float    g_s[NMAX];            // row exp-sum (unnormalized)
__device__ float    g_rowsum[NMAX];       // rowsum of adj .* P (UNnormalized)
__device__ int      g_count[NMAX];        // row degree
__device__ int      g_off[NMAX + 1];      // CSR offsets
__device__ int      g_bsum[1024];         // scan block sums
__device__ float    g_feat1[NMAX];
__device__ float    g_feat2[NMAX];
__device__ float    g_ev[EMAX];           // exp(leaky(e)) per edge (COO order)
__device__ unsigned short g_rank[EMAX];   // within-row rank of each edge
__device__ int2     g_cu[EMAX];           // CSR interleaved (col, UNnormalized ex-bits)
__device__ __align__(256) __half g_xh[(size_t)NMAX * FDIM];  // fp16 copy of x
__device__ __align__(256) __half g_hA[(size_t)NMAX * FDIM];  // fp16 update hop1
__device__ __align__(256) __half g_hB[(size_t)NMAX * FDIM];  // fp16 update hop2

// ---------------- kernels ----------------

// feat1/feat2 dot products + fused x->fp16 conversion + per-row state init.
__global__ void k_feats(const float* __restrict__ x, const float* __restrict__ a, int n) {
    int gw = (blockIdx.x * blockDim.x + threadIdx.x) >> 5;
    int lane = threadIdx.x & 31;
    if (gw >= n) return;
    float4 v  = __ldg((const float4*)(x + (size_t)gw * FDIM) + lane);
    float4 a1 = __ldg((const float4*)a + lane);
    float4 a2 = __ldg((const float4*)(a + FDIM) + lane);

    __half2 h0 = __floats2half2_rn(v.x, v.y);
    __half2 h1 = __floats2half2_rn(v.z, v.w);
    uint2 packed;
    packed.x = *(unsigned*)&h0;
    packed.y = *(unsigned*)&h1;
    ((uint2*)g_xh)[(size_t)gw * 32 + lane] = packed;

    float d1 = v.x * a1.x + v.y * a1.y + v.z * a1.z + v.w * a1.w;
    float d2 = v.x * a2.x + v.y * a2.y + v.z * a2.z + v.w * a2.w;
    #pragma unroll
    for (int o = 16; o; o >>= 1) {
        d1 += __shfl_down_sync(0xffffffffu, d1, o);
        d2 += __shfl_down_sync(0xffffffffu, d2, o);
    }
    if (lane == 0) {
        g_feat1[gw] = d1; g_feat2[gw] = d2;
        g_s[gw] = 0.f; g_rowsum[gw] = 0.f; g_count[gw] = 0;
    }
}

// edge pass: exp(leaky(e)), row sum, degree+rank, unnormalized rowsum
__global__ void k_edge1(const int* __restrict__ row, const int* __restrict__ col,
                        const float* __restrict__ adj, int e) {
    int j = blockIdx.x * blockDim.x + threadIdx.x;
    if (j >= e) return;
    int r = row[j];
    float ev = __ldg(&g_feat1[r]) + __ldg(&g_feat2[col[j]]);
    ev = (ev >= 0.f) ? ev : 0.2f * ev;
    float ex = __expf(ev);
    g_ev[j] = ex;
    atomicAdd(&g_s[r], ex);
    atomicAdd(&g_rowsum[r], 0.5f * adj[j] * ex);
    int rank = atomicAdd(&g_count[r], 1);
    g_rank[j] = (unsigned short)rank;
}

// scan 1: warp-shuffle per-1024-block exclusive scan of degrees
__global__ void k_scan1(int n) {
    __shared__ int warp_tot[32];
    int i = blockIdx.x * 1024 + threadIdx.x;
    int lane = threadIdx.x & 31, wid = threadIdx.x >> 5;
    int v = (i < n) ? g_count[i] : 0;
    int s = v;
    #pragma unroll
    for (int o = 1; o < 32; o <<= 1) {
        int t = __shfl_up_sync(0xffffffffu, s, o);
        if (lane >= o) s += t;
    }
    if (lane == 31) warp_tot[wid] = s;
    __syncthreads();
    if (wid == 0) {
        int w = warp_tot[lane];
        #pragma unroll
        for (int o = 1; o < 32; o <<= 1) {
            int t = __shfl_up_sync(0xffffffffu, w, o);
            if (lane >= o) w += t;
        }
        warp_tot[lane] = w;
    }
    __syncthreads();
    int base = wid ? warp_tot[wid - 1] : 0;
    if (i < n) g_off[i] = base + s - v;            // exclusive
    if (threadIdx.x == 1023) g_bsum[blockIdx.x] = base + s;
}

// scan 2+3 fused (R12-proven 1024-thread version)
__global__ void k_scan23(int nb, int n) {
    __shared__ int s_prefix;
    int b = blockIdx.x;
    if (threadIdx.x < 32) {
        int acc = 0;
        for (int i = threadIdx.x; i < b; i += 32) acc += g_bsum[i];
        #pragma unroll
        for (int o = 16; o; o >>= 1) acc += __shfl_down_sync(0xffffffffu, acc, o);
        if (threadIdx.x == 0) s_prefix = acc;
    }
    __syncthreads();
    int prefix = s_prefix;
    int i = b * 1024 + threadIdx.x;
    if (i < n) g_off[i] += prefix;
    if (b == nb - 1 && threadIdx.x == 0) g_off[n] = prefix + g_bsum[nb - 1];
}

// scatter: UNnormalized ex into interleaved CSR. No atomics, no g_s read.
__global__ void k_scatter(const int* __restrict__ row, const int* __restrict__ col, int e) {
    int j = blockIdx.x * blockDim.x + threadIdx.x;
    if (j >= e) return;
    int r = row[j];
    int pos = __ldg(&g_off[r]) + (int)g_rank[j];
    int2 cu;
    cu.x = col[j];
    cu.y = __float_as_int(g_ev[j]);           // UNnormalized; SpMM scales by 1/s
    g_cu[pos] = cu;
}

// ---- SpMM helpers ----

// Gather one row's edges: first tile preloaded in cu0; remainder (rare) loops.
__device__ __forceinline__ float4 row_gather(const uint2* __restrict__ in_upd, int lane,
                                             int beg, int deg, int2 cu0) {
    float4 acc = make_float4(0.f, 0.f, 0.f, 0.f);
    int m = min(32, deg);
    #pragma unroll 8
    for (int t = 0; t < m; t++) {
        int   cc = __shfl_sync(0xffffffffu, cu0.x, t);
        float uu = __int_as_float(__shfl_sync(0xffffffffu, cu0.y, t));
        uint2 raw = __ldg(in_upd + (size_t)cc * 32 + lane);
        float2 f0 = __half22float2(*(__half2*)&raw.x);
        float2 f1 = __half22float2(*(__half2*)&raw.y);
        acc.x += uu * f0.x;
        acc.y += uu * f0.y;
        acc.z += uu * f1.x;
        acc.w += uu * f1.y;
    }
    for (int j0 = 32; j0 < deg; j0 += 32) {       // rare: degree > 32
        int2 cu = make_int2(0, 0);
        if (j0 + lane < deg) cu = __ldg(&g_cu[beg + j0 + lane]);
        int mm = min(32, deg - j0);
        #pragma unroll 8
        for (int t = 0; t < mm; t++) {
            int   cc = __shfl_sync(0xffffffffu, cu.x, t);
            float uu = __int_as_float(__shfl_sync(0xffffffffu, cu.y, t));
            uint2 raw = __ldg(in_upd + (size_t)cc * 32 + lane);
            float2 f0 = __half22float2(*(__half2*)&raw.x);
            float2 f1 = __half22float2(*(__half2*)&raw.y);
            acc.x += uu * f0.x;
            acc.y += uu * f0.y;
            acc.z += uu * f1.x;
            acc.w += uu * f1.y;
        }
    }
    return acc;
}

__device__ __forceinline__ void row_epilogue(int r, int lane, int step, float4 acc,
                                             float* __restrict__ out, float c0, float c1) {
    // normalize: CSR holds unnormalized ex, scale by 1/s here (once per row)
    float s = __ldg(&g_s[r]);
    float inv_s = (s > 0.f) ? 1.f / s : 0.f;
    acc.x *= inv_s; acc.y *= inv_s; acc.z *= inv_s; acc.w *= inv_s;

    size_t v2idx = (size_t)r * 32 + lane;
    if (step < 2) {
        __half2 h0 = __floats2half2_rn(acc.x, acc.y);
        __half2 h1 = __floats2half2_rn(acc.z, acc.w);
        uint2 packed;
        packed.x = *(unsigned*)&h0;
        packed.y = *(unsigned*)&h1;
        ((uint2*)(step == 0 ? g_hA : g_hB))[v2idx] = packed;
    } else {
        float rs0 = __ldg(&g_rowsum[r]) * inv_s;
        float rs1 = rs0 * c0;
        float rs2 = rs1 * c1;
        float w0 = 0.009f * (1.f - 0.9f * rs0);
        float w1 = 0.09f  * (1.f - 0.9f * rs1);
        float w2 = 0.9f   * (1.f - 0.9f * rs2);

        uint2 rawx = ((const uint2*)g_xh)[v2idx];
        uint2 rawa = ((const uint2*)g_hA)[v2idx];
        uint2 rawb = ((const uint2*)g_hB)[v2idx];
        float2 x0 = __half22float2(*(__half2*)&rawx.x);
        float2 x1 = __half22float2(*(__half2*)&rawx.y);
        float2 a0 = __half22float2(*(__half2*)&rawa.x);
        float2 a1 = __half22float2(*(__half2*)&rawa.y);
        float2 b0 = __half22float2(*(__half2*)&rawb.x);
        float2 b1 = __half22float2(*(__half2*)&rawb.y);
        float4 o;
        o.x = 0.001f * x0.x + w0 * a0.x + w1 * b0.x + w2 * acc.x;
        o.y = 0.001f * x0.y + w0 * a0.y + w1 * b0.y + w2 * acc.y;
        o.z = 0.001f * x1.x + w0 * a1.x + w1 * b1.x + w2 * acc.z;
        o.w = 0.001f * x1.y + w0 * a1.y + w1 * b1.y + w2 * acc.w;
        ((float4*)out)[(size_t)r * (FDIM / 4) + lane] = o;
    }
}

// fused SpMM: TWO rows per warp, processed SEQUENTIALLY with both rows'
// metadata (off + first cu tile) prefetched up front.  (R12-proven.)
__global__ void __launch_bounds__(256) k_spmm(float* __restrict__ out,
                                              const float* __restrict__ cheb,
                                              int step, int n) {
    int warp = (blockIdx.x * blockDim.x + threadIdx.x) >> 5;
    int lane = threadIdx.x & 31;
    int r0 = warp * 2;
    if (r0 >= n) return;
    bool has2 = (r0 + 1 < n);

    const uint2* in_upd = (const uint2*)((step == 0) ? g_xh : ((step == 1) ? g_hA : g_hB));

    int o0 = __ldg(&g_off[r0]);
    int o1 = __ldg(&g_off[r0 + 1]);
    int o2 = has2 ? __ldg(&g_off[r0 + 2]) : o1;
    int deg0 = o1 - o0;
    int deg1 = o2 - o1;
    int2 cu0 = make_int2(0, 0), cu1 = make_int2(0, 0);
    if (lane < deg0) cu0 = __ldg(&g_cu[o0 + lane]);
    if (lane < deg1) cu1 = __ldg(&g_cu[o1 + lane]);

    float c0 = 0.f, c1 = 0.f;
    if (step == 2) {
        c0 = 1.f / (1.f + __expf(-__ldg(&cheb[0])));
        c1 = 1.f / (1.f + __expf(-__ldg(&cheb[1])));
    }

    float4 acc0 = row_gather(in_upd, lane, o0, deg0, cu0);
    row_epilogue(r0, lane, step, acc0, out, c0, c1);

    if (has2) {
        float4 acc1 = row_gather(in_upd, lane, o1, deg1, cu1);
        row_epilogue(r0 + 1, lane, step, acc1, out, c0, c1);
    }
}

// ---------------- launch ----------------
extern "C" void kernel_launch(void* const* d_in, const int* in_sizes, int n_in,
                              void* d_out, int out_size) {
    const float* x    = (const float*)d_in[0];
    const float* a    = (const float*)d_in[2];
    const float* cheb = (const float*)d_in[4];
    const float* adj  = (const float*)d_in[5];
    const int*   row  = (const int*)d_in[6];
    const int*   col  = (const int*)d_in[7];
    float* out = (float*)d_out;

    int n = in_sizes[0] / FDIM;
    int e = in_sizes[5];

    k_feats<<<((size_t)n * 32 + 255) / 256, 256>>>(x, a, n);
    k_edge1<<<(e + 255) / 256, 256>>>(row, col, adj, e);

    int nb = (n + 1023) / 1024;
    k_scan1<<<nb, 1024>>>(n);
    k_scan23<<<nb, 1024>>>(nb, n);

    k_scatter<<<(e + 255) / 256, 256>>>(row, col, e);

    // 8 warps/block, 2 rows per warp -> 16 rows per block
    int spmm_blocks = (n + 15) / 16;
    for (int step = 0; step < 3; step++)
        k_spmm<<<spmm_blocks, 256>>>(out, cheb, step, n);
}

// round 15
// speedup vs baseline: 1.1721x; 1.0091x over previous
#include <cuda_runtime.h>
#include <cuda_fp16.h>
#include <cstddef>

#define NMAX 100000
#define EMAX 1600000
#define FDIM 128

// ---------------- static scratch (no allocs allowed) ----------------
__device__ float    g_rowsum[NMAX];       // rowsum of adj .* P (UNnormalized)
__device__ int      g_count[NMAX];        // row degree
__device__ int      g_off[NMAX + 1];      // CSR offsets
__device__ int      g_bsum[1024];         // scan block sums
__device__ float    g_feat1[NMAX];
__device__ float    g_feat2[NMAX];
__device__ float    g_ev[EMAX];           // exp(leaky(e)) per edge (COO order)
__device__ unsigned short g_rank[EMAX];   // within-row rank of each edge
__device__ int2     g_cu[EMAX];           // CSR interleaved (col, UNnormalized ex-bits)
__device__ __align__(256) __half g_xh[(size_t)NMAX * FDIM];  // fp16 copy of x
__device__ __align__(256) __half g_hA[(size_t)NMAX * FDIM];  // fp16 update hop1
__device__ __align__(256) __half g_hB[(size_t)NMAX * FDIM];  // fp16 update hop2

// ---------------- kernels ----------------

// feat1/feat2 dot products + fused x->fp16 conversion + per-row state init.
__global__ void k_feats(const float* __restrict__ x, const float* __restrict__ a, int n) {
    int gw = (blockIdx.x * blockDim.x + threadIdx.x) >> 5;
    int lane = threadIdx.x & 31;
    if (gw >= n) return;
    float4 v  = __ldg((const float4*)(x + (size_t)gw * FDIM) + lane);
    float4 a1 = __ldg((const float4*)a + lane);
    float4 a2 = __ldg((const float4*)(a + FDIM) + lane);

    __half2 h0 = __floats2half2_rn(v.x, v.y);
    __half2 h1 = __floats2half2_rn(v.z, v.w);
    uint2 packed;
    packed.x = *(unsigned*)&h0;
    packed.y = *(unsigned*)&h1;
    ((uint2*)g_xh)[(size_t)gw * 32 + lane] = packed;

    float d1 = v.x * a1.x + v.y * a1.y + v.z * a1.z + v.w * a1.w;
    float d2 = v.x * a2.x + v.y * a2.y + v.z * a2.z + v.w * a2.w;
    #pragma unroll
    for (int o = 16; o; o >>= 1) {
        d1 += __shfl_down_sync(0xffffffffu, d1, o);
        d2 += __shfl_down_sync(0xffffffffu, d2, o);
    }
    if (lane == 0) {
        g_feat1[gw] = d1; g_feat2[gw] = d2;
        g_rowsum[gw] = 0.f; g_count[gw] = 0;
    }
}

// edge pass: exp(leaky(e)), degree+rank, unnormalized rowsum. (No s atomic:
// the softmax denominator is re-derived in-register inside the SpMM.)
__global__ void k_edge1(const int* __restrict__ row, const int* __restrict__ col,
                        const float* __restrict__ adj, int e) {
    int j = blockIdx.x * blockDim.x + threadIdx.x;
    if (j >= e) return;
    int r = row[j];
    float ev = __ldg(&g_feat1[r]) + __ldg(&g_feat2[col[j]]);
    ev = (ev >= 0.f) ? ev : 0.2f * ev;
    float ex = __expf(ev);
    g_ev[j] = ex;
    atomicAdd(&g_rowsum[r], 0.5f * adj[j] * ex);
    int rank = atomicAdd(&g_count[r], 1);
    g_rank[j] = (unsigned short)rank;
}

// scan 1: warp-shuffle per-1024-block exclusive scan of degrees
__global__ void k_scan1(int n) {
    __shared__ int warp_tot[32];
    int i = blockIdx.x * 1024 + threadIdx.x;
    int lane = threadIdx.x & 31, wid = threadIdx.x >> 5;
    int v = (i < n) ? g_count[i] : 0;
    int s = v;
    #pragma unroll
    for (int o = 1; o < 32; o <<= 1) {
        int t = __shfl_up_sync(0xffffffffu, s, o);
        if (lane >= o) s += t;
    }
    if (lane == 31) warp_tot[wid] = s;
    __syncthreads();
    if (wid == 0) {
        int w = warp_tot[lane];
        #pragma unroll
        for (int o = 1; o < 32; o <<= 1) {
            int t = __shfl_up_sync(0xffffffffu, w, o);
            if (lane >= o) w += t;
        }
        warp_tot[lane] = w;
    }
    __syncthreads();
    int base = wid ? warp_tot[wid - 1] : 0;
    if (i < n) g_off[i] = base + s - v;            // exclusive
    if (threadIdx.x == 1023) g_bsum[blockIdx.x] = base + s;
}

// scan 2+3 fused
__global__ void k_scan23(int nb, int n) {
    __shared__ int s_prefix;
    int b = blockIdx.x;
    if (threadIdx.x < 32) {
        int acc = 0;
        for (int i = threadIdx.x; i < b; i += 32) acc += g_bsum[i];
        #pragma unroll
        for (int o = 16; o; o >>= 1) acc += __shfl_down_sync(0xffffffffu, acc, o);
        if (threadIdx.x == 0) s_prefix = acc;
    }
    __syncthreads();
    int prefix = s_prefix;
    int i = b * 1024 + threadIdx.x;
    if (i < n) g_off[i] += prefix;
    if (b == nb - 1 && threadIdx.x == 0) g_off[n] = prefix + g_bsum[nb - 1];
}

// scatter: UNnormalized ex into interleaved CSR. No atomics, no g_s read.
__global__ void k_scatter(const int* __restrict__ row, const int* __restrict__ col, int e) {
    int j = blockIdx.x * blockDim.x + threadIdx.x;
    if (j >= e) return;
    int r = row[j];
    int pos = __ldg(&g_off[r]) + (int)g_rank[j];
    int2 cu;
    cu.x = col[j];
    cu.y = __float_as_int(g_ev[j]);           // UNnormalized; SpMM scales by 1/s
    g_cu[pos] = cu;
}

// ---- SpMM helpers ----

// Gather one row's edges; also accumulates the softmax denominator s = sum(ex).
// First tile preloaded in cu0; remainder (rare) loops.
__device__ __forceinline__ float4 row_gather(const uint2* __restrict__ in_upd, int lane,
                                             int beg, int deg, int2 cu0, float& ssum) {
    float4 acc = make_float4(0.f, 0.f, 0.f, 0.f);
    float s = 0.f;
    int m = min(32, deg);
    #pragma unroll 8
    for (int t = 0; t < m; t++) {
        int   cc = __shfl_sync(0xffffffffu, cu0.x, t);
        float uu = __int_as_float(__shfl_sync(0xffffffffu, cu0.y, t));
        s += uu;
        uint2 raw = __ldg(in_upd + (size_t)cc * 32 + lane);
        float2 f0 = __half22float2(*(__half2*)&raw.x);
        float2 f1 = __half22float2(*(__half2*)&raw.y);
        acc.x += uu * f0.x;
        acc.y += uu * f0.y;
        acc.z += uu * f1.x;
        acc.w += uu * f1.y;
    }
    for (int j0 = 32; j0 < deg; j0 += 32) {       // rare: degree > 32
        int2 cu = make_int2(0, 0);
        if (j0 + lane < deg) cu = __ldg(&g_cu[beg + j0 + lane]);
        int mm = min(32, deg - j0);
        #pragma unroll 8
        for (int t = 0; t < mm; t++) {
            int   cc = __shfl_sync(0xffffffffu, cu.x, t);
            float uu = __int_as_float(__shfl_sync(0xffffffffu, cu.y, t));
            s += uu;
            uint2 raw = __ldg(in_upd + (size_t)cc * 32 + lane);
            float2 f0 = __half22float2(*(__half2*)&raw.x);
            float2 f1 = __half22float2(*(__half2*)&raw.y);
            acc.x += uu * f0.x;
            acc.y += uu * f0.y;
            acc.z += uu * f1.x;
            acc.w += uu * f1.y;
        }
    }
    ssum = s;
    return acc;
}

__device__ __forceinline__ void row_epilogue(int r, int lane, int step, float4 acc,
                                             float s, float* __restrict__ out,
                                             float c0, float c1) {
    float inv_s = (s > 0.f) ? 1.f / s : 0.f;
    acc.x *= inv_s; acc.y *= inv_s; acc.z *= inv_s; acc.w *= inv_s;

    size_t v2idx = (size_t)r * 32 + lane;
    if (step < 2) {
        __half2 h0 = __floats2half2_rn(acc.x, acc.y);
        __half2 h1 = __floats2half2_rn(acc.z, acc.w);
        uint2 packed;
        packed.x = *(unsigned*)&h0;
        packed.y = *(unsigned*)&h1;
        ((uint2*)(step == 0 ? g_hA : g_hB))[v2idx] = packed;
    } else {
        float rs0 = __ldg(&g_rowsum[r]) * inv_s;
        float rs1 = rs0 * c0;
        float rs2 = rs1 * c1;
        float w0 = 0.009f * (1.f - 0.9f * rs0);
        float w1 = 0.09f  * (1.f - 0.9f * rs1);
        float w2 = 0.9f   * (1.f - 0.9f * rs2);

        uint2 rawx = ((const uint2*)g_xh)[v2idx];
        uint2 rawa = ((const uint2*)g_hA)[v2idx];
        uint2 rawb = ((const uint2*)g_hB)[v2idx];
        float2 x0 = __half22float2(*(__half2*)&rawx.x);
        float2 x1 = __half22float2(*(__half2*)&rawx.y);
        float2 a0 = __half22float2(*(__half2*)&rawa.x);
        float2 a1 = __half22float2(*(__half2*)&rawa.y);
        float2 b0 = __half22float2(*(__half2*)&rawb.x);
        float2 b1 = __half22float2(*(__half2*)&rawb.y);
        float4 o;
        o.x = 0.001f * x0.x + w0 * a0.x + w1 * b0.x + w2 * acc.x;
        o.y = 0.001f * x0.y + w0 * a0.y + w1 * b0.y + w2 * acc.y;
        o.z = 0.001f * x1.x + w0 * a1.x + w1 * b1.x + w2 * acc.z;
        o.w = 0.001f * x1.y + w0 * a1.y + w1 * b1.y + w2 * acc.w;
        ((float4*)out)[(size_t)r * (FDIM / 4) + lane] = o;
    }
}

// fused SpMM: TWO rows per warp, processed SEQUENTIALLY with both rows'
// metadata (off + first cu tile) prefetched up front.  (R12/R14-proven.)
__global__ void __launch_bounds__(256) k_spmm(float* __restrict__ out,
                                              const float* __restrict__ cheb,
                                              int step, int n) {
    int warp = (blockIdx.x * blockDim.x + threadIdx.x) >> 5;
    int lane = threadIdx.x & 31;
    int r0 = warp * 2;
    if (r0 >= n) return;
    bool has2 = (r0 + 1 < n);

    const uint2* in_upd = (const uint2*)((step == 0) ? g_xh : ((step == 1) ? g_hA : g_hB));

    int o0 = __ldg(&g_off[r0]);
    int o1 = __ldg(&g_off[r0 + 1]);
    int o2 = has2 ? __ldg(&g_off[r0 + 2]) : o1;
    int deg0 = o1 - o0;
    int deg1 = o2 - o1;
    int2 cu0 = make_int2(0, 0), cu1 = make_int2(0, 0);
    if (lane < deg0) cu0 = __ldg(&g_cu[o0 + lane]);
    if (lane < deg1) cu1 = __ldg(&g_cu[o1 + lane]);

    float c0 = 0.f, c1 = 0.f;
    if (step == 2) {
        c0 = 1.f / (1.f + __expf(-__ldg(&cheb[0])));
        c1 = 1.f / (1.f + __expf(-__ldg(&cheb[1])));
    }

    float s0;
    float4 acc0 = row_gather(in_upd, lane, o0, deg0, cu0, s0);
    row_epilogue(r0, lane, step, acc0, s0, out, c0, c1);

    if (has2) {
        float s1;
        float4 acc1 = row_gather(in_upd, lane, o1, deg1, cu1, s1);
        row_epilogue(r0 + 1, lane, step, acc1, s1, out, c0, c1);
    }
}

// ---------------- launch ----------------
extern "C" void kernel_launch(void* const* d_in, const int* in_sizes, int n_in,
                              void* d_out, int out_size) {
    const float* x    = (const float*)d_in[0];
    const float* a    = (const float*)d_in[2];
    const float* cheb = (const float*)d_in[4];
    const float* adj  = (const float*)d_in[5];
    const int*   row  = (const int*)d_in[6];
    const int*   col  = (const int*)d_in[7];
    float* out = (float*)d_out;

    int n = in_sizes[0] / FDIM;
    int e = in_sizes[5];

    k_feats<<<((size_t)n * 32 + 255) / 256, 256>>>(x, a, n);
    k_edge1<<<(e + 255) / 256, 256>>>(row, col, adj, e);

    int nb = (n + 1023) / 1024;
    k_scan1<<<nb, 1024>>>(n);
    k_scan23<<<nb, 1024>>>(nb, n);

    k_scatter<<<(e + 255) / 256, 256>>>(row, col, e);

    // 8 warps/block, 2 rows per warp -> 16 rows per block
    int spmm_blocks = (n + 15) / 16;
    for (int step = 0; step < 3; step++)
        k_spmm<<<spmm_blocks, 256>>>(out, cheb, step, n);
}

// round 16
// speedup vs baseline: 1.1940x; 1.0187x over previous
#include <cuda_runtime.h>
#include <cuda_fp16.h>
#include <cstddef>

#define NMAX 100000
#define EMAX 1600000
#define FDIM 128
#define READY_BIT 0x40000000

// ---------------- static scratch (no allocs allowed) ----------------
__device__ float    g_rowsum[NMAX];       // rowsum of adj .* P (UNnormalized)
__device__ int      g_count[NMAX];        // row degree
__device__ int      g_off[NMAX + 1];      // CSR offsets
__device__ int      g_flag[1024];         // scan aggregate flags (READY_BIT | total)
__device__ float    g_feat1[NMAX];
__device__ float    g_feat2[NMAX];
__device__ float    g_ev[EMAX];           // exp(leaky(e)) per edge (COO order)
__device__ unsigned short g_rank[EMAX];   // within-row rank of each edge
__device__ int2     g_cu[EMAX];           // CSR interleaved (col*32, UNnorm ex-bits)
__device__ __align__(256) __half g_xh[(size_t)NMAX * FDIM];  // fp16 copy of x
__device__ __align__(256) __half g_hA[(size_t)NMAX * FDIM];  // fp16 update hop1
__device__ __align__(256) __half g_hB[(size_t)NMAX * FDIM];  // fp16 update hop2

// ---------------- kernels ----------------

// feat1/feat2 dot products + fused x->fp16 conversion + per-row state init.
__global__ void k_feats(const float* __restrict__ x, const float* __restrict__ a, int n) {
    int gw = (blockIdx.x * blockDim.x + threadIdx.x) >> 5;
    int lane = threadIdx.x & 31;
    if (gw >= n) return;
    float4 v  = __ldg((const float4*)(x + (size_t)gw * FDIM) + lane);
    float4 a1 = __ldg((const float4*)a + lane);
    float4 a2 = __ldg((const float4*)(a + FDIM) + lane);

    __half2 h0 = __floats2half2_rn(v.x, v.y);
    __half2 h1 = __floats2half2_rn(v.z, v.w);
    uint2 packed;
    packed.x = *(unsigned*)&h0;
    packed.y = *(unsigned*)&h1;
    ((uint2*)g_xh)[(size_t)gw * 32 + lane] = packed;

    float d1 = v.x * a1.x + v.y * a1.y + v.z * a1.z + v.w * a1.w;
    float d2 = v.x * a2.x + v.y * a2.y + v.z * a2.z + v.w * a2.w;
    #pragma unroll
    for (int o = 16; o; o >>= 1) {
        d1 += __shfl_down_sync(0xffffffffu, d1, o);
        d2 += __shfl_down_sync(0xffffffffu, d2, o);
    }
    if (lane == 0) {
        g_feat1[gw] = d1; g_feat2[gw] = d2;
        g_rowsum[gw] = 0.f; g_count[gw] = 0;
        if (gw < 1024) g_flag[gw] = 0;
    }
}

// edge pass: exp(leaky(e)), degree+rank, unnormalized rowsum.
__global__ void k_edge1(const int* __restrict__ row, const int* __restrict__ col,
                        const float* __restrict__ adj, int e) {
    int j = blockIdx.x * blockDim.x + threadIdx.x;
    if (j >= e) return;
    int r = row[j];
    float ev = __ldg(&g_feat1[r]) + __ldg(&g_feat2[col[j]]);
    ev = (ev >= 0.f) ? ev : 0.2f * ev;
    float ex = __expf(ev);
    g_ev[j] = ex;
    atomicAdd(&g_rowsum[r], 0.5f * adj[j] * ex);
    int rank = atomicAdd(&g_count[r], 1);
    g_rank[j] = (unsigned short)rank;
}

// single-kernel scan: per-block shuffle scan + decoupled aggregate lookback.
// 98 blocks <= SM count: all co-resident, spin is safe.
__global__ void k_scan(int nb, int n) {
    __shared__ int warp_tot[32];
    __shared__ int s_prefix;
    int b = blockIdx.x;
    int i = b * 1024 + threadIdx.x;
    int lane = threadIdx.x & 31, wid = threadIdx.x >> 5;
    int v = (i < n) ? g_count[i] : 0;
    int s = v;
    #pragma unroll
    for (int o = 1; o < 32; o <<= 1) {
        int t = __shfl_up_sync(0xffffffffu, s, o);
        if (lane >= o) s += t;
    }
    if (lane == 31) warp_tot[wid] = s;
    __syncthreads();
    if (wid == 0) {
        int w = warp_tot[lane];
        #pragma unroll
        for (int o = 1; o < 32; o <<= 1) {
            int t = __shfl_up_sync(0xffffffffu, w, o);
            if (lane >= o) w += t;
        }
        warp_tot[lane] = w;
    }
    __syncthreads();
    int base = wid ? warp_tot[wid - 1] : 0;
    int block_tot = warp_tot[31];
    // publish aggregate FIRST
    if (threadIdx.x == 0) {
        atomicExch(&g_flag[b], block_tot | READY_BIT);
        s_prefix = 0;
    }
    __syncthreads();
    if (threadIdx.x < 32) {
        int acc = 0;
        for (int p = lane; p < b; p += 32) {
            int f;
            do { f = atomicAdd(&g_flag[p], 0); } while (!(f & READY_BIT));
            acc += f & (READY_BIT - 1);
        }
        #pragma unroll
        for (int o = 16; o; o >>= 1) acc += __shfl_down_sync(0xffffffffu, acc, o);
        if (lane == 0) s_prefix = acc;
    }
    __syncthreads();
    int prefix = s_prefix;
    if (i < n) g_off[i] = prefix + base + s - v;           // exclusive
    if (b == nb - 1 && threadIdx.x == 0) g_off[n] = prefix + block_tot;
}

// scatter: UNnormalized ex + pre-scaled col into interleaved CSR. No atomics.
__global__ void k_scatter(const int* __restrict__ row, const int* __restrict__ col, int e) {
    int j = blockIdx.x * blockDim.x + threadIdx.x;
    if (j >= e) return;
    int r = row[j];
    int pos = __ldg(&g_off[r]) + (int)g_rank[j];
    int2 cu;
    cu.x = col[j] * 32;                        // pre-scaled uint2-row offset
    cu.y = __float_as_int(g_ev[j]);            // UNnormalized; SpMM scales by 1/s
    g_cu[pos] = cu;
}

// ---- SpMM ----
// TWO rows per warp, sequential, metadata prefetched and staged in SMEM so the
// hot loop uses LDS broadcast at immediate offsets (no shfl). STEP templated.

template <int STEP>
__global__ void __launch_bounds__(256) k_spmm(float* __restrict__ out,
                                              const float* __restrict__ cheb, int n) {
    __shared__ int2 s_cu[8][64];
    int wip  = threadIdx.x >> 5;               // warp in block
    int warp = (blockIdx.x * 256 + threadIdx.x) >> 5;
    int lane = threadIdx.x & 31;
    int r0 = warp * 2;
    if (r0 >= n) return;
    bool has2 = (r0 + 1 < n);

    const uint2* in_upd = (STEP == 0) ? (const uint2*)g_xh
                        : (STEP == 1) ? (const uint2*)g_hA : (const uint2*)g_hB;

    int o0 = __ldg(&g_off[r0]);
    int o1 = __ldg(&g_off[r0 + 1]);
    int o2 = has2 ? __ldg(&g_off[r0 + 2]) : o1;
    int deg0 = o1 - o0;
    int deg1 = o2 - o1;
    int2 cu0 = make_int2(0, 0), cu1 = make_int2(0, 0);
    if (lane < deg0) cu0 = __ldg(&g_cu[o0 + lane]);
    if (lane < deg1) cu1 = __ldg(&g_cu[o1 + lane]);
    s_cu[wip][lane]      = cu0;
    s_cu[wip][32 + lane] = cu1;
    __syncwarp();

    float c0 = 0.f, c1 = 0.f;
    if (STEP == 2) {
        c0 = 1.f / (1.f + __expf(-__ldg(&cheb[0])));
        c1 = 1.f / (1.f + __expf(-__ldg(&cheb[1])));
    }

    #pragma unroll
    for (int rr = 0; rr < 2; rr++) {
        int r   = r0 + rr;
        if (rr == 1 && !has2) break;
        int beg = rr ? o1 : o0;
        int deg = rr ? deg1 : deg0;

        float4 acc = make_float4(0.f, 0.f, 0.f, 0.f);
        float s = 0.f;
        int m = min(32, deg);
        const int2* tile = &s_cu[wip][rr * 32];
        #pragma unroll 8
        for (int t = 0; t < m; t++) {
            int2 cu = tile[t];                  // LDS.64 broadcast, imm offset
            float uu = __int_as_float(cu.y);
            s += uu;
            uint2 raw = __ldg(in_upd + (size_t)(cu.x + lane));
            float2 f0 = __half22float2(*(__half2*)&raw.x);
            float2 f1 = __half22float2(*(__half2*)&raw.y);
            acc.x += uu * f0.x;
            acc.y += uu * f0.y;
            acc.z += uu * f1.x;
            acc.w += uu * f1.y;
        }
        for (int j0 = 32; j0 < deg; j0 += 32) {     // rare: degree > 32 (shfl path)
            int2 cu = make_int2(0, 0);
            if (j0 + lane < deg) cu = __ldg(&g_cu[beg + j0 + lane]);
            int mm = min(32, deg - j0);
            for (int t = 0; t < mm; t++) {
                int   cc = __shfl_sync(0xffffffffu, cu.x, t);
                float uu = __int_as_float(__shfl_sync(0xffffffffu, cu.y, t));
                s += uu;
                uint2 raw = __ldg(in_upd + (size_t)(cc + lane));
                float2 f0 = __half22float2(*(__half2*)&raw.x);
                float2 f1 = __half22float2(*(__half2*)&raw.y);
                acc.x += uu * f0.x;
                acc.y += uu * f0.y;
                acc.z += uu * f1.x;
                acc.w += uu * f1.y;
            }
        }

        float inv_s = (s > 0.f) ? 1.f / s : 0.f;
        acc.x *= inv_s; acc.y *= inv_s; acc.z *= inv_s; acc.w *= inv_s;

        size_t v2idx = (size_t)r * 32 + lane;
        if (STEP < 2) {
            __half2 h0 = __floats2half2_rn(acc.x, acc.y);
            __half2 h1 = __floats2half2_rn(acc.z, acc.w);
            uint2 packed;
            packed.x = *(unsigned*)&h0;
            packed.y = *(unsigned*)&h1;
            ((uint2*)(STEP == 0 ? g_hA : g_hB))[v2idx] = packed;
        } else {
            float rs0 = __ldg(&g_rowsum[r]) * inv_s;
            float rs1 = rs0 * c0;
            float rs2 = rs1 * c1;
            float w0 = 0.009f * (1.f - 0.9f * rs0);
            float w1 = 0.09f  * (1.f - 0.9f * rs1);
            float w2 = 0.9f   * (1.f - 0.9f * rs2);

            uint2 rawx = ((const uint2*)g_xh)[v2idx];
            uint2 rawa = ((const uint2*)g_hA)[v2idx];
            uint2 rawb = ((const uint2*)g_hB)[v2idx];
            float2 x0 = __half22float2(*(__half2*)&rawx.x);
            float2 x1 = __half22float2(*(__half2*)&rawx.y);
            float2 a0 = __half22float2(*(__half2*)&rawa.x);
            float2 a1 = __half22float2(*(__half2*)&rawa.y);
            float2 b0 = __half22float2(*(__half2*)&rawb.x);
            float2 b1 = __half22float2(*(__half2*)&rawb.y);
            float4 o;
            o.x = 0.001f * x0.x + w0 * a0.x + w1 * b0.x + w2 * acc.x;
            o.y = 0.001f * x0.y + w0 * a0.y + w1 * b0.y + w2 * acc.y;
            o.z = 0.001f * x1.x + w0 * a1.x + w1 * b1.x + w2 * acc.z;
            o.w = 0.001f * x1.y + w0 * a1.y + w1 * b1.y + w2 * acc.w;
            ((float4*)out)[(size_t)r * (FDIM / 4) + lane] = o;
        }
    }
}

// ---------------- launch ----------------
extern "C" void kernel_launch(void* const* d_in, const int* in_sizes, int n_in,
                              void* d_out, int out_size) {
    const float* x    = (const float*)d_in[0];
    const float* a    = (const float*)d_in[2];
    const float* cheb = (const float*)d_in[4];
    const float* adj  = (const float*)d_in[5];
    const int*   row  = (const int*)d_in[6];
    const int*   col  = (const int*)d_in[7];
    float* out = (float*)d_out;

    int n = in_sizes[0] / FDIM;
    int e = in_sizes[5];

    k_feats<<<((size_t)n * 32 + 255) / 256, 256>>>(x, a, n);
    k_edge1<<<(e + 255) / 256, 256>>>(row, col, adj, e);

    int nb = (n + 1023) / 1024;
    k_scan<<<nb, 1024>>>(nb, n);

    k_scatter<<<(e + 255) / 256, 256>>>(row, col, e);

    int spmm_blocks = (n + 15) / 16;   // 8 warps/block, 2 rows/warp
    k_spmm<0><<<spmm_blocks, 256>>>(out, cheb, n);
    k_spmm<1><<<spmm_blocks, 256>>>(out, cheb, n);
    k_spmm<2><<<spmm_blocks, 256>>>(out, cheb, n);
}